// round 5
// baseline (speedup 1.0000x reference)
#include <cuda_runtime.h>
#include <math.h>

#define TT 256
#define HH 512
#define LN_EPS 1e-5f
#define NB 256        // persistent grid size
#define KSPL 128      // K-chunk for split-K=4 over K=512

// ---------------- scratch (device globals; no allocation) ----------------
__device__ float g_zp[4][TT*HH];   // partials of h@U
__device__ float g_sp[4][TT*HH];   // partials of z@W
__device__ float g_Sp[4][TT*TT];   // partials of z@u^T
__device__ float g_R1p[2][TT*HH];  // partials of S@d
__device__ float g_R2p[2][TT*HH];  // partials of S@(d.*P)
__device__ float g_z [TT*HH];
__device__ float g_u [TT*HH];      // h .* z
__device__ float g_s [TT*HH];      // z@W + b
__device__ float g_d [TT*HH];
__device__ float g_P [TT*HH];      // column-wise inclusive cumsum of h
__device__ float g_c [TT];         // row sums of h
__device__ unsigned g_count;       // barrier counter (reset by k_reset each call)

__global__ void k_reset() { g_count = 0u; }

// ---------------- device-wide barrier (monotonic count, per-launch reset) ----
__device__ __forceinline__ void gbar(unsigned& phase) {
    __syncthreads();
    if (threadIdx.x == 0) {
        __threadfence();
        atomicAdd(&g_count, 1u);
        const unsigned target = (phase + 1u) * (unsigned)NB;
        while (*(volatile unsigned*)&g_count < target) { }
        __threadfence();
    }
    phase++;
    __syncthreads();
}

// ---------------- smem pool offsets: 3 x [2][32][34] float ----------------
#define OPA 0
#define OPB 2176
#define OPC 4352

// ---------------- 32x32 NN partial tile, K-chunk=128, double buffered -------
__device__ __forceinline__ void gemm_nn_tile(
    float* __restrict__ sm,
    const float* __restrict__ A, const float* __restrict__ B,
    float* __restrict__ Cp, int N, int K,
    int row0, int col0, int kbase)
{
    float* sA = sm + OPA;   // [buf][kk][row]
    float* sB = sm + OPB;   // [buf][kk][col]
    const int tid = threadIdx.x;
    const int tx = tid & 15, ty = tid >> 4;
    const int r_ld = tid >> 5, c_ld = tid & 31;

    #pragma unroll
    for (int i = 0; i < 4; i++) {
        int r = r_ld + i * 8;
        sA[c_ld * 34 + r] = A[(row0 + r) * K + kbase + c_ld];
        sB[r * 34 + c_ld] = B[(kbase + r) * N + col0 + c_ld];
    }
    __syncthreads();

    float acc00=0.f, acc01=0.f, acc10=0.f, acc11=0.f;
    float a_reg[4], b_reg[4];

    #pragma unroll
    for (int t = 0; t < 4; t++) {
        const int boff = (t & 1) * 1088;
        if (t < 3) {
            const int k0 = kbase + (t + 1) * 32;
            #pragma unroll
            for (int i = 0; i < 4; i++) {
                int r = r_ld + i * 8;
                a_reg[i] = A[(row0 + r) * K + k0 + c_ld];
                b_reg[i] = B[(k0 + r) * N + col0 + c_ld];
            }
        }
        #pragma unroll
        for (int kk = 0; kk < 32; kk++) {
            float2 av = *(const float2*)&sA[boff + kk * 34 + 2 * ty];
            float2 bv = *(const float2*)&sB[boff + kk * 34 + 2 * tx];
            acc00 += av.x * bv.x; acc01 += av.x * bv.y;
            acc10 += av.y * bv.x; acc11 += av.y * bv.y;
        }
        if (t < 3) {
            const int o2 = boff ^ 1088;
            #pragma unroll
            for (int i = 0; i < 4; i++) {
                int r = r_ld + i * 8;
                sA[o2 + c_ld * 34 + r] = a_reg[i];
                sB[o2 + r * 34 + c_ld] = b_reg[i];
            }
        }
        __syncthreads();
    }

    const int rr0 = row0 + 2 * ty, cc0 = col0 + 2 * tx;
    *(float2*)&Cp[ rr0      * N + cc0] = make_float2(acc00, acc01);
    *(float2*)&Cp[(rr0 + 1) * N + cc0] = make_float2(acc10, acc11);
}

// ---------------- 32x32 NT partial tile (C[t,i] = sum_k A[t,k]B[i,k]) -------
__device__ __forceinline__ void gemm_nt_tile(
    float* __restrict__ sm,
    const float* __restrict__ A, const float* __restrict__ B,
    float* __restrict__ Cp,
    int row0, int col0, int kbase)
{
    float* sA = sm + OPA;
    float* sB = sm + OPB;
    const int tid = threadIdx.x;
    const int tx = tid & 15, ty = tid >> 4;
    const int r_ld = tid >> 5, c_ld = tid & 31;

    #pragma unroll
    for (int i = 0; i < 4; i++) {
        int r = r_ld + i * 8;
        sA[c_ld * 34 + r] = A[(row0 + r) * HH + kbase + c_ld];
        sB[c_ld * 34 + r] = B[(col0 + r) * HH + kbase + c_ld] * 0.f + B[(col0 + r) * HH + kbase + c_ld];
    }
    __syncthreads();

    float acc00=0.f, acc01=0.f, acc10=0.f, acc11=0.f;
    float a_reg[4], b_reg[4];

    #pragma unroll
    for (int t = 0; t < 4; t++) {
        const int boff = (t & 1) * 1088;
        if (t < 3) {
            const int k0 = kbase + (t + 1) * 32;
            #pragma unroll
            for (int i = 0; i < 4; i++) {
                int r = r_ld + i * 8;
                a_reg[i] = A[(row0 + r) * HH + k0 + c_ld];
                b_reg[i] = B[(col0 + r) * HH + k0 + c_ld];
            }
        }
        #pragma unroll
        for (int kk = 0; kk < 32; kk++) {
            float2 av = *(const float2*)&sA[boff + kk * 34 + 2 * ty];
            float2 bv = *(const float2*)&sB[boff + kk * 34 + 2 * tx];
            acc00 += av.x * bv.x; acc01 += av.x * bv.y;
            acc10 += av.y * bv.x; acc11 += av.y * bv.y;
        }
        if (t < 3) {
            const int o2 = boff ^ 1088;
            #pragma unroll
            for (int i = 0; i < 4; i++) {
                int r = r_ld + i * 8;
                sA[o2 + c_ld * 34 + r] = a_reg[i];
                sB[o2 + c_ld * 34 + r] = b_reg[i];
            }
        }
        __syncthreads();
    }

    const int rr0 = row0 + 2 * ty, cc0 = col0 + 2 * tx;
    *(float2*)&Cp[ rr0      * TT + cc0] = make_float2(acc00, acc01);
    *(float2*)&Cp[(rr0 + 1) * TT + cc0] = make_float2(acc10, acc11);
}

// ---------------- block reductions ----------------
__device__ __forceinline__ float2 brsum2(float a, float b, float2* sh) {
    #pragma unroll
    for (int o = 16; o; o >>= 1) {
        a += __shfl_xor_sync(0xffffffffu, a, o);
        b += __shfl_xor_sync(0xffffffffu, b, o);
    }
    if ((threadIdx.x & 31) == 0) sh[threadIdx.x >> 5] = make_float2(a, b);
    __syncthreads();
    float sa = 0.f, sb = 0.f;
    #pragma unroll
    for (int i = 0; i < 8; i++) { sa += sh[i].x; sb += sh[i].y; }
    __syncthreads();
    return make_float2(sa, sb);
}
__device__ __forceinline__ float brsum1(float a, float2* sh) {
    #pragma unroll
    for (int o = 16; o; o >>= 1) a += __shfl_xor_sync(0xffffffffu, a, o);
    if ((threadIdx.x & 31) == 0) sh[threadIdx.x >> 5].x = a;
    __syncthreads();
    float s = 0.f;
    #pragma unroll
    for (int i = 0; i < 8; i++) s += sh[i].x;
    __syncthreads();
    return s;
}

// =====================================================================
// Persistent kernel: all 6 stages, 5 device-wide barriers
// =====================================================================
__global__ __launch_bounds__(256, 2) void k_all(
    const float* __restrict__ h, const float* __restrict__ U,
    const float* __restrict__ W, const float* __restrict__ av,
    const float* __restrict__ bv, const float* __restrict__ gamma,
    const float* __restrict__ beta, const int* __restrict__ targets,
    float* __restrict__ out)
{
    __shared__ __align__(16) float pool[3 * 2176];
    __shared__ float2 shred[8];
    const int bid = blockIdx.x;
    const int tid = threadIdx.x;
    unsigned phase = 0;

    // ===== Stage A: z partials (2 tiles/block) + prep (P, c) =====
    #pragma unroll
    for (int i = 0; i < 2; i++) {
        const int tile = bid + NB * i;          // 0..511
        const int sp = tile >> 7, t = tile & 127;
        gemm_nn_tile(pool, h, U, g_zp[sp], HH, HH,
                     (t >> 4) * 32, (t & 15) * 32, sp * KSPL);
    }
    if (bid < 2) {
        const int q = bid * 256 + tid;
        float run = 0.f;
        for (int t = 0; t < TT; t++) {
            int idx = t * HH + q;
            run += h[idx];
            g_P[idx] = run;
        }
    } else if (bid < 34) {
        const int warp = tid >> 5, lane = tid & 31;
        const int row = (bid - 2) * 8 + warp;
        const float* hr = h + row * HH;
        float v = 0.f;
        #pragma unroll
        for (int j = 0; j < 16; j++) v += hr[lane + j * 32];
        #pragma unroll
        for (int o = 16; o; o >>= 1) v += __shfl_xor_sync(0xffffffffu, v, o);
        if (lane == 0) g_c[row] = v;
    }
    gbar(phase);

    // ===== Stage B: z = relu(sum partials + a), u = h.*z =====
    {
        const int gi = bid * 256 + tid;
        if (gi < (TT * HH) / 4) {
            const int e = gi * 4;
            const int col = e & (HH - 1);
            float4 p0 = *(const float4*)&g_zp[0][e];
            float4 p1 = *(const float4*)&g_zp[1][e];
            float4 p2 = *(const float4*)&g_zp[2][e];
            float4 p3 = *(const float4*)&g_zp[3][e];
            float4 aa = *(const float4*)&av[col];
            float4 hv = *(const float4*)&h[e];
            float4 z;
            z.x = fmaxf(p0.x + p1.x + p2.x + p3.x + aa.x, 0.f);
            z.y = fmaxf(p0.y + p1.y + p2.y + p3.y + aa.y, 0.f);
            z.z = fmaxf(p0.z + p1.z + p2.z + p3.z + aa.z, 0.f);
            z.w = fmaxf(p0.w + p1.w + p2.w + p3.w + aa.w, 0.f);
            *(float4*)&g_z[e] = z;
            *(float4*)&g_u[e] = make_float4(hv.x * z.x, hv.y * z.y, hv.z * z.z, hv.w * z.w);
        }
    }
    gbar(phase);

    // ===== Stage C: s partials (512 tiles) + scores partials (256 tiles) =====
    #pragma unroll
    for (int i = 0; i < 3; i++) {
        const int tile = bid + NB * i;          // 0..767
        if (tile < 512) {
            const int sp = tile >> 7, t = tile & 127;
            gemm_nn_tile(pool, g_z, W, g_sp[sp], HH, HH,
                         (t >> 4) * 32, (t & 15) * 32, sp * KSPL);
        } else {
            const int b = tile - 512;
            const int sp = b >> 6, t = b & 63;
            gemm_nt_tile(pool, g_z, g_u, g_Sp[sp],
                         (t >> 3) * 32, (t & 7) * 32, sp * KSPL);
        }
    }
    gbar(phase);

    // ===== Stage D: s finalize + LN/CE backward -> d (1 row/block) =====
    {
        const int t = bid;
        const int i0 = t * HH + tid, i1 = i0 + 256;
        float s0 = g_sp[0][i0] + g_sp[1][i0] + g_sp[2][i0] + g_sp[3][i0] + bv[tid];
        float s1 = g_sp[0][i1] + g_sp[1][i1] + g_sp[2][i1] + g_sp[3][i1] + bv[tid + 256];
        g_s[i0] = s0; g_s[i1] = s1;

        float2 r = brsum2(s0 + s1, s0 * s0 + s1 * s1, shred);
        float mu = r.x * (1.f / HH);
        float var = r.y * (1.f / HH) - mu * mu;
        float sinv = rsqrtf(var + LN_EPS);
        float xh0 = (s0 - mu) * sinv, xh1 = (s1 - mu) * sinv;

        float ga0 = gamma[tid], ga1 = gamma[tid + 256];
        float y0 = xh0 * ga0 + beta[tid];
        float y1 = xh1 * ga1 + beta[tid + 256];

        float p0 = __expf(y0), p1 = __expf(y1);   // LN-bounded, no max-sub needed
        float Zs = brsum1(p0 + p1, shred);
        float inv = 1.f / Zs;
        p0 *= inv; p1 *= inv;

        const int tgt = targets[t];
        float gg0 = ga0 * (p0 - (tid == tgt ? 1.f : 0.f));
        float gg1 = ga1 * (p1 - (tid + 256 == tgt ? 1.f : 0.f));

        float2 m2 = brsum2(gg0 + gg1, gg0 * xh0 + gg1 * xh1, shred);
        float mg  = m2.x * (1.f / HH);
        float mgx = m2.y * (1.f / HH);

        g_d[i0] = sinv * (gg0 - mg - xh0 * mgx);
        g_d[i1] = sinv * (gg1 - mg - xh1 * mgx);
    }
    gbar(phase);

    // ===== Stage E: dual GEMM split-K=2, S summed+masked inline (1 tile/block)
    {
        float* sA  = pool + OPA;
        float* sB1 = pool + OPB;
        float* sB2 = pool + OPC;
        const int sp = bid >> 7, tb = bid & 127;
        const int row0 = (tb >> 4) * 32, col0 = (tb & 15) * 32;
        const int kbase = sp * 128;
        const int tx = tid & 15, ty = tid >> 4;
        const int r_ld = tid >> 5, c_ld = tid & 31;

        #pragma unroll
        for (int i = 0; i < 4; i++) {
            int r = r_ld + i * 8;
            int tt = row0 + r, ii = kbase + c_ld;
            int sidx = tt * TT + ii;
            float v = g_Sp[0][sidx] + g_Sp[1][sidx] + g_Sp[2][sidx] + g_Sp[3][sidx];
            sA[c_ld * 34 + r] = (ii < tt) ? (v + g_c[ii]) : 0.f;
            int bidx = (kbase + r) * HH + col0 + c_ld;
            float dv = g_d[bidx];
            sB1[r * 34 + c_ld] = dv;
            sB2[r * 34 + c_ld] = dv * g_P[bidx];
        }
        __syncthreads();

        float a00=0.f,a01=0.f,a10=0.f,a11=0.f;
        float b00=0.f,b01=0.f,b10=0.f,b11=0.f;
        float a_reg[4], d_reg[4], q_reg[4];

        #pragma unroll
        for (int t = 0; t < 4; t++) {
            const int boff = (t & 1) * 1088;
            if (t < 3) {
                const int k0 = kbase + (t + 1) * 32;
                #pragma unroll
                for (int i = 0; i < 4; i++) {
                    int r = r_ld + i * 8;
                    int tt = row0 + r, ii = k0 + c_ld;
                    int sidx = tt * TT + ii;
                    float v = g_Sp[0][sidx] + g_Sp[1][sidx] + g_Sp[2][sidx] + g_Sp[3][sidx];
                    a_reg[i] = (ii < tt) ? (v + g_c[ii]) : 0.f;
                    int bidx = (k0 + r) * HH + col0 + c_ld;
                    float dv = g_d[bidx];
                    d_reg[i] = dv;
                    q_reg[i] = dv * g_P[bidx];
                }
            }
            #pragma unroll
            for (int kk = 0; kk < 32; kk++) {
                float2 sv = *(const float2*)&sA [boff + kk * 34 + 2 * ty];
                float2 dv = *(const float2*)&sB1[boff + kk * 34 + 2 * tx];
                float2 qv = *(const float2*)&sB2[boff + kk * 34 + 2 * tx];
                a00 += sv.x * dv.x; a01 += sv.x * dv.y;
                a10 += sv.y * dv.x; a11 += sv.y * dv.y;
                b00 += sv.x * qv.x; b01 += sv.x * qv.y;
                b10 += sv.y * qv.x; b11 += sv.y * qv.y;
            }
            if (t < 3) {
                const int o2 = boff ^ 1088;
                #pragma unroll
                for (int i = 0; i < 4; i++) {
                    int r = r_ld + i * 8;
                    sA [o2 + c_ld * 34 + r] = a_reg[i];
                    sB1[o2 + r * 34 + c_ld] = d_reg[i];
                    sB2[o2 + r * 34 + c_ld] = q_reg[i];
                }
            }
            __syncthreads();
        }

        const int rr0 = row0 + 2 * ty, cc0 = col0 + 2 * tx;
        *(float2*)&g_R1p[sp][ rr0      * HH + cc0] = make_float2(a00, a01);
        *(float2*)&g_R1p[sp][(rr0 + 1) * HH + cc0] = make_float2(a10, a11);
        *(float2*)&g_R2p[sp][ rr0      * HH + cc0] = make_float2(b00, b01);
        *(float2*)&g_R2p[sp][(rr0 + 1) * HH + cc0] = make_float2(b10, b11);
    }
    gbar(phase);

    // ===== Stage F: pre = s - (P*R1 - R2); out = LN(pre) (1 row/block) =====
    {
        const int t = bid;
        const int i0 = t * HH + tid, i1 = i0 + 256;

        float r1a = g_R1p[0][i0] + g_R1p[1][i0];
        float r1b = g_R1p[0][i1] + g_R1p[1][i1];
        float r2a = g_R2p[0][i0] + g_R2p[1][i0];
        float r2b = g_R2p[0][i1] + g_R2p[1][i1];

        float pre0 = g_s[i0] - (g_P[i0] * r1a - r2a);
        float pre1 = g_s[i1] - (g_P[i1] * r1b - r2b);

        float2 r = brsum2(pre0 + pre1, pre0 * pre0 + pre1 * pre1, shred);
        float mu = r.x * (1.f / HH);
        float var = r.y * (1.f / HH) - mu * mu;
        float sinv = rsqrtf(var + LN_EPS);

        out[i0] = (pre0 - mu) * sinv * gamma[tid]       + beta[tid];
        out[i1] = (pre1 - mu) * sinv * gamma[tid + 256] + beta[tid + 256];
    }
}

// ---------------- launch ----------------
extern "C" void kernel_launch(void* const* d_in, const int* in_sizes, int n_in,
                              void* d_out, int out_size) {
    const float* h      = (const float*)d_in[0];
    const float* U      = (const float*)d_in[1];
    const float* W      = (const float*)d_in[2];
    const float* a      = (const float*)d_in[3];
    const float* b      = (const float*)d_in[4];
    const float* gamma  = (const float*)d_in[5];
    const float* beta   = (const float*)d_in[6];
    const int*   tgt    = (const int*)  d_in[7];
    float*       out    = (float*)d_out;

    k_reset<<<1, 1>>>();
    k_all<<<NB, 256>>>(h, U, W, a, b, gamma, beta, tgt, out);
}

// round 8
// speedup vs baseline: 1.3707x; 1.3707x over previous
#include <cuda_runtime.h>
#include <math.h>

#define TT 256
#define HH 512
#define LN_EPS 1e-5f

// ---------------- scratch (device globals; no allocation) ----------------
__device__ float g_zp[4][TT*HH];   // partials of h@U
__device__ float g_sp[4][TT*HH];   // partials of z@W
__device__ float g_Sp[4][TT*TT];   // partials of z@u^T
__device__ float g_S [TT*TT];      // finalized causal scores
__device__ float g_R1p[4][TT*HH];  // partials of S@d
__device__ float g_R2p[4][TT*HH];  // partials of S@(d.*P)
__device__ float g_z [TT*HH];
__device__ float g_u [TT*HH];      // h .* z
__device__ float g_s [TT*HH];      // z@W + b
__device__ float g_d [TT*HH];
__device__ float g_P [TT*HH];      // column-wise inclusive cumsum of h
__device__ float g_c [TT];         // row sums of h

// =====================================================================
// 64x64 tile, 256 threads, 4x4 micro, double-buffered, k-tile = 16.
// Per kk per thread: 2 x LDS.128 + 16 FFMA  (FMA-pipe bound).
// =====================================================================
template<int NKT>  // number of 16-deep k-tiles (kchunk = NKT*16)
__device__ __forceinline__ void gemm64_nn(
    const float* __restrict__ A, const float* __restrict__ B,
    float* __restrict__ Cp, int N, int K,
    int row0, int col0, int kbase)
{
    __shared__ __align__(16) float sA[2][16][68];   // [buf][kk][row]
    __shared__ __align__(16) float sB[2][16][68];   // [buf][kk][col]
    const int tid = threadIdx.x;
    const int tx = tid & 15, ty = tid >> 4;
    const int arow = tid >> 2, akg = (tid & 3) * 4;   // A loader: row, k-subgroup
    const int bkr = tid >> 4, bcg = (tid & 15) * 4;   // B loader: k-row, col-group

    float4 va = *(const float4*)&A[(row0 + arow) * K + kbase + akg];
    float4 vb = *(const float4*)&B[(kbase + bkr) * N + col0 + bcg];
    sA[0][akg + 0][arow] = va.x;
    sA[0][akg + 1][arow] = va.y;
    sA[0][akg + 2][arow] = va.z;
    sA[0][akg + 3][arow] = va.w;
    *(float4*)&sB[0][bkr][bcg] = vb;
    __syncthreads();

    float acc[4][4] = {};

    #pragma unroll
    for (int t = 0; t < NKT; t++) {
        const int buf = t & 1;
        if (t + 1 < NKT) {
            const int k0 = kbase + (t + 1) * 16;
            va = *(const float4*)&A[(row0 + arow) * K + k0 + akg];
            vb = *(const float4*)&B[(k0 + bkr) * N + col0 + bcg];
        }
        #pragma unroll
        for (int kk = 0; kk < 16; kk++) {
            float4 a4 = *(const float4*)&sA[buf][kk][4 * ty];
            float4 b4 = *(const float4*)&sB[buf][kk][4 * tx];
            acc[0][0] += a4.x * b4.x; acc[0][1] += a4.x * b4.y; acc[0][2] += a4.x * b4.z; acc[0][3] += a4.x * b4.w;
            acc[1][0] += a4.y * b4.x; acc[1][1] += a4.y * b4.y; acc[1][2] += a4.y * b4.z; acc[1][3] += a4.y * b4.w;
            acc[2][0] += a4.z * b4.x; acc[2][1] += a4.z * b4.y; acc[2][2] += a4.z * b4.z; acc[2][3] += a4.z * b4.w;
            acc[3][0] += a4.w * b4.x; acc[3][1] += a4.w * b4.y; acc[3][2] += a4.w * b4.z; acc[3][3] += a4.w * b4.w;
        }
        if (t + 1 < NKT) {
            const int nb = buf ^ 1;
            sA[nb][akg + 0][arow] = va.x;
            sA[nb][akg + 1][arow] = va.y;
            sA[nb][akg + 2][arow] = va.z;
            sA[nb][akg + 3][arow] = va.w;
            *(float4*)&sB[nb][bkr][bcg] = vb;
        }
        __syncthreads();
    }

    const int orow = row0 + 4 * ty, ocol = col0 + 4 * tx;
    #pragma unroll
    for (int r = 0; r < 4; r++)
        *(float4*)&Cp[(orow + r) * N + ocol] =
            make_float4(acc[r][0], acc[r][1], acc[r][2], acc[r][3]);
}

// NT variant: C[r, c] = sum_k A[r, k] * B[c, k]   (both K-major)
template<int NKT>
__device__ __forceinline__ void gemm64_nt(
    const float* __restrict__ A, const float* __restrict__ B,
    float* __restrict__ Cp, int N, int K,
    int row0, int col0, int kbase)
{
    __shared__ __align__(16) float sA[2][16][68];
    __shared__ __align__(16) float sB[2][16][68];
    const int tid = threadIdx.x;
    const int tx = tid & 15, ty = tid >> 4;
    const int arow = tid >> 2, akg = (tid & 3) * 4;

    float4 va = *(const float4*)&A[(row0 + arow) * K + kbase + akg];
    float4 vb = *(const float4*)&B[(col0 + arow) * K + kbase + akg];
    sA[0][akg + 0][arow] = va.x;
    sA[0][akg + 1][arow] = va.y;
    sA[0][akg + 2][arow] = va.z;
    sA[0][akg + 3][arow] = va.w;
    sB[0][akg + 0][arow] = vb.x;
    sB[0][akg + 1][arow] = vb.y;
    sB[0][akg + 2][arow] = vb.z;
    sB[0][akg + 3][arow] = vb.w;
    __syncthreads();

    float acc[4][4] = {};

    #pragma unroll
    for (int t = 0; t < NKT; t++) {
        const int buf = t & 1;
        if (t + 1 < NKT) {
            const int k0 = kbase + (t + 1) * 16;
            va = *(const float4*)&A[(row0 + arow) * K + k0 + akg];
            vb = *(const float4*)&B[(col0 + arow) * K + k0 + akg];
        }
        #pragma unroll
        for (int kk = 0; kk < 16; kk++) {
            float4 a4 = *(const float4*)&sA[buf][kk][4 * ty];
            float4 b4 = *(const float4*)&sB[buf][kk][4 * tx];
            acc[0][0] += a4.x * b4.x; acc[0][1] += a4.x * b4.y; acc[0][2] += a4.x * b4.z; acc[0][3] += a4.x * b4.w;
            acc[1][0] += a4.y * b4.x; acc[1][1] += a4.y * b4.y; acc[1][2] += a4.y * b4.z; acc[1][3] += a4.y * b4.w;
            acc[2][0] += a4.z * b4.x; acc[2][1] += a4.z * b4.y; acc[2][2] += a4.z * b4.z; acc[2][3] += a4.z * b4.w;
            acc[3][0] += a4.w * b4.x; acc[3][1] += a4.w * b4.y; acc[3][2] += a4.w * b4.z; acc[3][3] += a4.w * b4.w;
        }
        if (t + 1 < NKT) {
            const int nb = buf ^ 1;
            sA[nb][akg + 0][arow] = va.x;
            sA[nb][akg + 1][arow] = va.y;
            sA[nb][akg + 2][arow] = va.z;
            sA[nb][akg + 3][arow] = va.w;
            sB[nb][akg + 0][arow] = vb.x;
            sB[nb][akg + 1][arow] = vb.y;
            sB[nb][akg + 2][arow] = vb.z;
            sB[nb][akg + 3][arow] = vb.w;
        }
        __syncthreads();
    }

    const int orow = row0 + 4 * ty, ocol = col0 + 4 * tx;
    #pragma unroll
    for (int r = 0; r < 4; r++)
        *(float4*)&Cp[(orow + r) * N + ocol] =
            make_float4(acc[r][0], acc[r][1], acc[r][2], acc[r][3]);
}

// ===== K1: z partials (128 CTAs) + prep P/c (34 CTAs) =====
__global__ __launch_bounds__(256) void k1(const float* __restrict__ h,
                                          const float* __restrict__ U) {
    const int bid = blockIdx.x;
    if (bid < 128) {
        const int sp = bid >> 5, tile = bid & 31;
        gemm64_nn<8>(h, U, g_zp[sp], HH, HH,
                     (tile >> 3) * 64, (tile & 7) * 64, sp * 128);
    } else {
        const int b = bid - 128;
        if (b < 2) {
            const int q = b * 256 + threadIdx.x;
            float run = 0.f;
            for (int t = 0; t < TT; t++) {
                int idx = t * HH + q;
                run += h[idx];
                g_P[idx] = run;
            }
        } else {
            const int warp = threadIdx.x >> 5, lane = threadIdx.x & 31;
            const int row = (b - 2) * 8 + warp;
            const float* hr = h + row * HH;
            float v = 0.f;
            #pragma unroll
            for (int j = 0; j < 16; j++) v += hr[lane + j * 32];
            #pragma unroll
            for (int o = 16; o; o >>= 1) v += __shfl_xor_sync(0xffffffffu, v, o);
            if (lane == 0) g_c[row] = v;
        }
    }
}

// ===== K2: z = relu(sum partials + a), u = h.*z  (128 CTAs) =====
__global__ __launch_bounds__(256) void k2(const float* __restrict__ h,
                                          const float* __restrict__ a) {
    const int e = (blockIdx.x * 256 + threadIdx.x) * 4;
    const int col = e & (HH - 1);
    float4 p0 = *(const float4*)&g_zp[0][e];
    float4 p1 = *(const float4*)&g_zp[1][e];
    float4 p2 = *(const float4*)&g_zp[2][e];
    float4 p3 = *(const float4*)&g_zp[3][e];
    float4 aa = *(const float4*)&a[col];
    float4 hv = *(const float4*)&h[e];
    float4 z;
    z.x = fmaxf(p0.x + p1.x + p2.x + p3.x + aa.x, 0.f);
    z.y = fmaxf(p0.y + p1.y + p2.y + p3.y + aa.y, 0.f);
    z.z = fmaxf(p0.z + p1.z + p2.z + p3.z + aa.z, 0.f);
    z.w = fmaxf(p0.w + p1.w + p2.w + p3.w + aa.w, 0.f);
    *(float4*)&g_z[e] = z;
    *(float4*)&g_u[e] = make_float4(hv.x * z.x, hv.y * z.y, hv.z * z.z, hv.w * z.w);
}

// ===== K3: s partials (128 CTAs) + scores partials (64 CTAs) =====
__global__ __launch_bounds__(256) void k3(const float* __restrict__ W) {
    const int bid = blockIdx.x;
    if (bid < 128) {
        const int sp = bid >> 5, tile = bid & 31;
        gemm64_nn<8>(g_z, W, g_sp[sp], HH, HH,
                     (tile >> 3) * 64, (tile & 7) * 64, sp * 128);
    } else {
        const int b = bid - 128;
        const int sp = b >> 4, tile = b & 15;
        gemm64_nt<8>(g_z, g_u, g_Sp[sp], TT, HH,
                     (tile >> 2) * 64, (tile & 3) * 64, sp * 128);
    }
}

// ---------------- block reductions ----------------
__device__ __forceinline__ float2 brsum2(float a, float b, float2* sh) {
    #pragma unroll
    for (int o = 16; o; o >>= 1) {
        a += __shfl_xor_sync(0xffffffffu, a, o);
        b += __shfl_xor_sync(0xffffffffu, b, o);
    }
    if ((threadIdx.x & 31) == 0) sh[threadIdx.x >> 5] = make_float2(a, b);
    __syncthreads();
    float sa = 0.f, sb = 0.f;
    #pragma unroll
    for (int i = 0; i < 8; i++) { sa += sh[i].x; sb += sh[i].y; }
    __syncthreads();
    return make_float2(sa, sb);
}
__device__ __forceinline__ float brsum1(float a, float2* sh) {
    #pragma unroll
    for (int o = 16; o; o >>= 1) a += __shfl_xor_sync(0xffffffffu, a, o);
    if ((threadIdx.x & 31) == 0) sh[threadIdx.x >> 5].x = a;
    __syncthreads();
    float s = 0.f;
    #pragma unroll
    for (int i = 0; i < 8; i++) s += sh[i].x;
    __syncthreads();
    return s;
}

// ===== K4: S finalize (mask + c) ; s finalize + LN/CE backward -> d =====
__global__ __launch_bounds__(256) void k4(const float* __restrict__ bias,
                                          const float* __restrict__ gamma,
                                          const float* __restrict__ beta,
                                          const int* __restrict__ targets) {
    __shared__ float2 sh[8];
    const int t = blockIdx.x;
    const int tid = threadIdx.x;

    // finalize one row of S: S[t, tid]
    {
        const int sidx = t * TT + tid;
        float v = g_Sp[0][sidx] + g_Sp[1][sidx] + g_Sp[2][sidx] + g_Sp[3][sidx];
        g_S[sidx] = (tid < t) ? (v + g_c[tid]) : 0.f;
    }

    const int i0 = t * HH + tid, i1 = i0 + 256;
    float s0 = g_sp[0][i0] + g_sp[1][i0] + g_sp[2][i0] + g_sp[3][i0] + bias[tid];
    float s1 = g_sp[0][i1] + g_sp[1][i1] + g_sp[2][i1] + g_sp[3][i1] + bias[tid + 256];
    g_s[i0] = s0; g_s[i1] = s1;

    float2 r = brsum2(s0 + s1, s0 * s0 + s1 * s1, sh);
    float mu = r.x * (1.f / HH);
    float var = r.y * (1.f / HH) - mu * mu;
    float sinv = rsqrtf(var + LN_EPS);
    float xh0 = (s0 - mu) * sinv, xh1 = (s1 - mu) * sinv;

    float ga0 = gamma[tid], ga1 = gamma[tid + 256];
    float y0 = xh0 * ga0 + beta[tid];
    float y1 = xh1 * ga1 + beta[tid + 256];

    float p0 = __expf(y0), p1 = __expf(y1);   // LN-bounded; no max-sub needed
    float Zs = brsum1(p0 + p1, sh);
    float inv = 1.f / Zs;
    p0 *= inv; p1 *= inv;

    const int tgt = targets[t];
    float gg0 = ga0 * (p0 - (tid == tgt ? 1.f : 0.f));
    float gg1 = ga1 * (p1 - (tid + 256 == tgt ? 1.f : 0.f));

    float2 m2 = brsum2(gg0 + gg1, gg0 * xh0 + gg1 * xh1, sh);
    float mg  = m2.x * (1.f / HH);
    float mgx = m2.y * (1.f / HH);

    g_d[i0] = sinv * (gg0 - mg - xh0 * mgx);
    g_d[i1] = sinv * (gg1 - mg - xh1 * mgx);
}

// ===== K5: dual GEMM R1 = S@d, R2 = S@(d.*P); split-K=4 (128 CTAs) =====
__global__ __launch_bounds__(256) void k5() {
    __shared__ __align__(16) float sA [2][16][68];
    __shared__ __align__(16) float sB1[2][16][68];
    __shared__ __align__(16) float sB2[2][16][68];
    const int bid = blockIdx.x;
    const int sp = bid >> 5, tile = bid & 31;
    const int row0 = (tile >> 3) * 64, col0 = (tile & 7) * 64;
    const int kbase = sp * 64;                  // K = TT = 256, kchunk = 64

    const int tid = threadIdx.x;
    const int tx = tid & 15, ty = tid >> 4;
    const int arow = tid >> 2, akg = (tid & 3) * 4;
    const int bkr = tid >> 4, bcg = (tid & 15) * 4;

    float4 va = *(const float4*)&g_S[(row0 + arow) * TT + kbase + akg];
    int bix = (kbase + bkr) * HH + col0 + bcg;
    float4 vd = *(const float4*)&g_d[bix];
    float4 vp = *(const float4*)&g_P[bix];
    sA[0][akg + 0][arow] = va.x;
    sA[0][akg + 1][arow] = va.y;
    sA[0][akg + 2][arow] = va.z;
    sA[0][akg + 3][arow] = va.w;
    *(float4*)&sB1[0][bkr][bcg] = vd;
    *(float4*)&sB2[0][bkr][bcg] =
        make_float4(vd.x * vp.x, vd.y * vp.y, vd.z * vp.z, vd.w * vp.w);
    __syncthreads();

    float a1[4][4] = {}, a2[4][4] = {};

    #pragma unroll
    for (int t = 0; t < 4; t++) {
        const int buf = t & 1;
        if (t < 3) {
            const int k0 = kbase + (t + 1) * 16;
            va = *(const float4*)&g_S[(row0 + arow) * TT + k0 + akg];
            bix = (k0 + bkr) * HH + col0 + bcg;
            vd = *(const float4*)&g_d[bix];
            vp = *(const float4*)&g_P[bix];
        }
        #pragma unroll
        for (int kk = 0; kk < 16; kk++) {
            float4 s4 = *(const float4*)&sA [buf][kk][4 * ty];
            float4 d4 = *(const float4*)&sB1[buf][kk][4 * tx];
            float4 q4 = *(const float4*)&sB2[buf][kk][4 * tx];
            a1[0][0] += s4.x * d4.x; a1[0][1] += s4.x * d4.y; a1[0][2] += s4.x * d4.z; a1[0][3] += s4.x * d4.w;
            a1[1][0] += s4.y * d4.x; a1[1][1] += s4.y * d4.y; a1[1][2] += s4.y * d4.z; a1[1][3] += s4.y * d4.w;
            a1[2][0] += s4.z * d4.x; a1[2][1] += s4.z * d4.y; a1[2][2] += s4.z * d4.z; a1[2][3] += s4.z * d4.w;
            a1[3][0] += s4.w * d4.x; a1[3][1] += s4.w * d4.y; a1[3][2] += s4.w * d4.z; a1[3][3] += s4.w * d4.w;
            a2[0][0] += s4.x * q4.x; a2[0][1] += s4.x * q4.y; a2[0][2] += s4.x * q4.z; a2[0][3] += s4.x * q4.w;
            a2[1][0] += s4.y * q4.x; a2[1][1] += s4.y * q4.y; a2[1][2] += s4.y * q4.z; a2[1][3] += s4.y * q4.w;
            a2[2][0] += s4.z * q4.x; a2[2][1] += s4.z * q4.y; a2[2][2] += s4.z * q4.z; a2[2][3] += s4.z * q4.w;
            a2[3][0] += s4.w * q4.x; a2[3][1] += s4.w * q4.y; a2[3][2] += s4.w * q4.z; a2[3][3] += s4.w * q4.w;
        }
        if (t < 3) {
            const int nb = buf ^ 1;
            sA[nb][akg + 0][arow] = va.x;
            sA[nb][akg + 1][arow] = va.y;
            sA[nb][akg + 2][arow] = va.z;
            sA[nb][akg + 3][arow] = va.w;
            *(float4*)&sB1[nb][bkr][bcg] = vd;
            *(float4*)&sB2[nb][bkr][bcg] =
                make_float4(vd.x * vp.x, vd.y * vp.y, vd.z * vp.z, vd.w * vp.w);
        }
        __syncthreads();
    }

    const int orow = row0 + 4 * ty, ocol = col0 + 4 * tx;
    #pragma unroll
    for (int r = 0; r < 4; r++) {
        *(float4*)&g_R1p[sp][(orow + r) * HH + ocol] =
            make_float4(a1[r][0], a1[r][1], a1[r][2], a1[r][3]);
        *(float4*)&g_R2p[sp][(orow + r) * HH + ocol] =
            make_float4(a2[r][0], a2[r][1], a2[r][2], a2[r][3]);
    }
}

// ===== K6: pre = s - (P*R1 - R2); out = LN(pre)  (256 CTAs) =====
__global__ __launch_bounds__(256) void k6(const float* __restrict__ gamma,
                                          const float* __restrict__ beta,
                                          float* __restrict__ out) {
    __shared__ float2 sh[8];
    const int t = blockIdx.x;
    const int tid = threadIdx.x;
    const int i0 = t * HH + tid, i1 = i0 + 256;

    float r1a = g_R1p[0][i0] + g_R1p[1][i0] + g_R1p[2][i0] + g_R1p[3][i0];
    float r1b = g_R1p[0][i1] + g_R1p[1][i1] + g_R1p[2][i1] + g_R1p[3][i1];
    float r2a = g_R2p[0][i0] + g_R2p[1][i0] + g_R2p[2][i0] + g_R2p[3][i0];
    float r2b = g_R2p[0][i1] + g_R2p[1][i1] + g_R2p[2][i1] + g_R2p[3][i1];

    float pre0 = g_s[i0] - (g_P[i0] * r1a - r2a);
    float pre1 = g_s[i1] - (g_P[i1] * r1b - r2b);

    float2 r = brsum2(pre0 + pre1, pre0 * pre0 + pre1 * pre1, sh);
    float mu = r.x * (1.f / HH);
    float var = r.y * (1.f / HH) - mu * mu;
    float sinv = rsqrtf(var + LN_EPS);

    out[i0] = (pre0 - mu) * sinv * gamma[tid]       + beta[tid];
    out[i1] = (pre1 - mu) * sinv * gamma[tid + 256] + beta[tid + 256];
}

// ---------------- launch ----------------
extern "C" void kernel_launch(void* const* d_in, const int* in_sizes, int n_in,
                              void* d_out, int out_size) {
    const float* h      = (const float*)d_in[0];
    const float* U      = (const float*)d_in[1];
    const float* W      = (const float*)d_in[2];
    const float* a      = (const float*)d_in[3];
    const float* b      = (const float*)d_in[4];
    const float* gamma  = (const float*)d_in[5];
    const float* beta   = (const float*)d_in[6];
    const int*   tgt    = (const int*)  d_in[7];
    float*       out    = (float*)d_out;

    dim3 blk(256);
    k1<<<162, blk>>>(h, U);                 // z partials + P + c
    k2<<<128, blk>>>(h, a);                 // z = relu(.), u = h.*z
    k3<<<192, blk>>>(W);                    // s partials + S partials
    k4<<<256, blk>>>(b, gamma, beta, tgt);  // S finalize + g_s + g_d
    k5<<<128, blk>>>();                     // R1/R2 partials
    k6<<<256, blk>>>(gamma, beta, out);     // final LN -> out
}